// round 1
// baseline (speedup 1.0000x reference)
#include <cuda_runtime.h>

#define CN 100000
#define CE 1600000

// ---- scratch (static __device__ — no allocation allowed) ----
__device__ float d_deg[CN];
__device__ float d_dinv[CN];
__device__ float d_norm[CE];
__device__ float d_hw[(size_t)CN * 64];
__device__ float d_agg[(size_t)CN * 64];
__device__ float d_emb[(size_t)CN * 64];
__device__ float d_stats[128];   // [0:64) sum, [64:128) sumsq
__device__ float d_ss[128];      // [0:64) scale, [64:128) shift

// ---- degree / norm precompute ----
__global__ void deg_init_k() {
    int n = blockIdx.x * 256 + threadIdx.x;
    if (n < CN) d_deg[n] = 1.0f;   // self-loop weight
}
__global__ void deg_acc_k(const int* __restrict__ dst, const float* __restrict__ ew) {
    int e = blockIdx.x * 256 + threadIdx.x;
    if (e < CE) atomicAdd(&d_deg[dst[e]], ew[e]);
}
__global__ void dinv_k() {
    int n = blockIdx.x * 256 + threadIdx.x;
    if (n < CN) d_dinv[n] = rsqrtf(d_deg[n]);
}
__global__ void norm_k(const int* __restrict__ src, const int* __restrict__ dst,
                       const float* __restrict__ ew) {
    int e = blockIdx.x * 256 + threadIdx.x;
    if (e < CE) d_norm[e] = d_dinv[src[e]] * ew[e] * d_dinv[dst[e]];
}

// ---- fused GEMM (+input GraphNorm/ReLU) (+output self-loop/bias init) ----
// MODE 0: in = x-channel (stride 128), out: d_agg = self_norm*hw + b
// MODE 1: in = relu(gn(d_agg)), out: d_emb  = 0.5*(self_norm*hw + b)
// MODE 2: in = relu(gn(d_agg)), out: d_emb += 0.5*(self_norm*hw + b)
template<int MODE>
__global__ __launch_bounds__(256) void gemm_k(const float* __restrict__ in,
                                              const float* __restrict__ W,
                                              const float* __restrict__ bias) {
    __shared__ float4 Ws[1024];          // 64x64 weight
    __shared__ float bs[64], sc[64], sh[64];
    int tid = threadIdx.x;
    const float4* Wv = (const float4*)W;
    #pragma unroll
    for (int i = 0; i < 4; i++) Ws[tid + i * 256] = Wv[tid + i * 256];
    if (tid < 64) {
        bs[tid] = bias[tid];
        if (MODE) { sc[tid] = d_ss[tid]; sh[tid] = d_ss[64 + tid]; }
    }
    __syncthreads();
    int n = blockIdx.x * 256 + tid;
    if (n >= CN) return;
    const float* row = (MODE == 0) ? (in + (size_t)n * 128)
                                   : (d_agg + (size_t)n * 64);
    float4 acc[16];
    #pragma unroll
    for (int j = 0; j < 16; j++) acc[j] = make_float4(0.f, 0.f, 0.f, 0.f);
    #pragma unroll 8
    for (int k = 0; k < 64; k++) {
        float xk = row[k];
        if (MODE) xk = fmaxf(fmaf(sc[k], xk, sh[k]), 0.f);
        #pragma unroll
        for (int j = 0; j < 16; j++) {
            float4 w = Ws[k * 16 + j];
            acc[j].x = fmaf(xk, w.x, acc[j].x);
            acc[j].y = fmaf(xk, w.y, acc[j].y);
            acc[j].z = fmaf(xk, w.z, acc[j].z);
            acc[j].w = fmaf(xk, w.w, acc[j].w);
        }
    }
    float dv = d_dinv[n], sn = dv * dv;
    float4* hwp = (float4*)(d_hw + (size_t)n * 64);
    float4* ob = (MODE == 0) ? (float4*)(d_agg + (size_t)n * 64)
                             : (float4*)(d_emb + (size_t)n * 64);
    #pragma unroll
    for (int j = 0; j < 16; j++) {
        float4 v = acc[j];
        hwp[j] = v;
        float4 b4 = *(const float4*)(bs + j * 4);
        float4 a;
        a.x = fmaf(sn, v.x, b4.x); a.y = fmaf(sn, v.y, b4.y);
        a.z = fmaf(sn, v.z, b4.z); a.w = fmaf(sn, v.w, b4.w);
        if (MODE >= 1) { a.x *= 0.5f; a.y *= 0.5f; a.z *= 0.5f; a.w *= 0.5f; }
        if (MODE == 2) { float4 o = ob[j]; a.x += o.x; a.y += o.y; a.z += o.z; a.w += o.w; }
        ob[j] = a;
    }
}

// ---- edge scatter: out[dst] += coef*norm[e]*hw[src], 16 threads/edge, red.v4 ----
template<int OUTBUF>   // 0 -> d_agg, 1 -> d_emb
__global__ __launch_bounds__(256) void scatter_k(const int* __restrict__ src,
                                                 const int* __restrict__ dst,
                                                 float coef) {
    int e = blockIdx.x * 16 + (threadIdx.x >> 4);
    if (e >= CE) return;
    int q = threadIdx.x & 15;
    int s = src[e], d = dst[e];
    float w = d_norm[e] * coef;
    float4 v = *(const float4*)(d_hw + (size_t)s * 64 + q * 4);
    float* base = OUTBUF ? d_emb : d_agg;
    float* p = base + (size_t)d * 64 + q * 4;
    asm volatile("red.global.add.v4.f32 [%0], {%1,%2,%3,%4};"
                 :: "l"(p), "f"(v.x * w), "f"(v.y * w), "f"(v.z * w), "f"(v.w * w)
                 : "memory");
}

// ---- GraphNorm stats ----
__global__ void zero_stats_k() { if (threadIdx.x < 128) d_stats[threadIdx.x] = 0.f; }

__global__ __launch_bounds__(256) void stats_k() {
    int tid = threadIdx.x;
    int j = tid & 63;
    float s = 0.f, sq = 0.f;
    for (int r = blockIdx.x * 4 + (tid >> 6); r < CN; r += gridDim.x * 4) {
        float v = d_agg[(size_t)r * 64 + j];
        s += v; sq = fmaf(v, v, sq);
    }
    __shared__ float sh1[256], sh2[256];
    sh1[tid] = s; sh2[tid] = sq;
    __syncthreads();
    if (tid < 64) {
        s  = sh1[tid] + sh1[tid + 64] + sh1[tid + 128] + sh1[tid + 192];
        sq = sh2[tid] + sh2[tid + 64] + sh2[tid + 128] + sh2[tid + 192];
        atomicAdd(&d_stats[tid], s);
        atomicAdd(&d_stats[64 + tid], sq);
    }
}

__global__ void finalize_k(const float* __restrict__ gnw, const float* __restrict__ gnb,
                           const float* __restrict__ gnms) {
    int j = threadIdx.x;
    const float invN = 1.0f / CN;
    float mean = d_stats[j] * invN;
    float ex2  = d_stats[64 + j] * invN;
    float ms = gnms[j];
    // var = E[(h - ms*mean)^2] = E[h^2] - ms*(2-ms)*mean^2
    float var = ex2 - ms * (2.0f - ms) * mean * mean;
    float scale = gnw[j] * rsqrtf(var + 1e-5f);
    d_ss[j] = scale;
    d_ss[64 + j] = gnb[j] - scale * ms * mean;
}

// ---- subgraph pool + MLP ----
__global__ __launch_bounds__(128) void pool_k(const int* __restrict__ subG,
                                              const float* __restrict__ mW1,
                                              const float* __restrict__ mb1,
                                              const float* __restrict__ mW2,
                                              const float* __restrict__ mb2,
                                              float* __restrict__ out) {
    __shared__ float Wm[64 * 128];
    __shared__ float pooled[64];
    __shared__ float ptmp[128];
    __shared__ float red[4];
    int tid = threadIdx.x, s = blockIdx.x;
    const float4* wv = (const float4*)mW1;
    #pragma unroll
    for (int i = 0; i < 16; i++) ((float4*)Wm)[tid + i * 128] = wv[tid + i * 128];
    int j = tid & 63, half = tid >> 6;
    float p = 0.f;
    #pragma unroll 4
    for (int m = half * 32; m < half * 32 + 32; m++) {
        int node = subG[s * 64 + m];
        p += d_emb[(size_t)node * 64 + j];
    }
    ptmp[tid] = p;
    __syncthreads();
    if (tid < 64) pooled[tid] = ptmp[tid] + ptmp[tid + 64];
    __syncthreads();
    float acc = mb1[tid];
    #pragma unroll 8
    for (int o = 0; o < 64; o++) acc = fmaf(pooled[o], Wm[o * 128 + tid], acc);
    float contrib = fmaxf(acc, 0.f) * mW2[tid];
    #pragma unroll
    for (int off = 16; off; off >>= 1) contrib += __shfl_xor_sync(0xffffffffu, contrib, off);
    if ((tid & 31) == 0) red[tid >> 5] = contrib;
    __syncthreads();
    if (tid == 0) out[s] = red[0] + red[1] + red[2] + red[3] + mb2[0];
}

extern "C" void kernel_launch(void* const* d_in, const int* in_sizes, int n_in,
                              void* d_out, int out_size) {
    const float* x    = (const float*)d_in[0];
    const int*   ei   = (const int*)d_in[1];
    const float* ew   = (const float*)d_in[2];
    const int*   subG = (const int*)d_in[3];
    const float* W1   = (const float*)d_in[4];
    const float* b1   = (const float*)d_in[5];
    const float* gnw  = (const float*)d_in[6];
    const float* gnb  = (const float*)d_in[7];
    const float* gnms = (const float*)d_in[8];
    const float* W2   = (const float*)d_in[9];
    const float* b2   = (const float*)d_in[10];
    const float* mW1  = (const float*)d_in[11];
    const float* mb1  = (const float*)d_in[12];
    const float* mW2  = (const float*)d_in[13];
    const float* mb2  = (const float*)d_in[14];
    float* out = (float*)d_out;
    const int* src = ei;
    const int* dst = ei + CE;

    const int nb = (CN + 255) / 256;
    const int eb = (CE + 255) / 256;

    deg_init_k<<<nb, 256>>>();
    deg_acc_k<<<eb, 256>>>(dst, ew);
    dinv_k<<<nb, 256>>>();
    norm_k<<<eb, 256>>>(src, dst, ew);

    for (int c = 0; c < 2; c++) {
        gemm_k<0><<<nb, 256>>>(x + c * 64, W1, b1);          // hw = x_c@W1, agg = sn*hw+b1
        scatter_k<0><<<CE / 16, 256>>>(src, dst, 1.0f);      // agg += norm*hw[src]
        zero_stats_k<<<1, 128>>>();
        stats_k<<<512, 256>>>();
        finalize_k<<<1, 64>>>(gnw, gnb, gnms);
        if (c == 0) gemm_k<1><<<nb, 256>>>(nullptr, W2, b2); // emb  = 0.5*(sn*hw2+b2)
        else        gemm_k<2><<<nb, 256>>>(nullptr, W2, b2); // emb += 0.5*(sn*hw2+b2)
        scatter_k<1><<<CE / 16, 256>>>(src, dst, 0.5f);      // emb += 0.5*norm*hw2[src]
    }
    pool_k<<<1000, 128>>>(subG, mW1, mb1, mW2, mb2, out);
}

// round 2
// speedup vs baseline: 1.8988x; 1.8988x over previous
#include <cuda_runtime.h>

#define CN 100000
#define CE 1600000
#define NB 391            // ceil(CN/256)

// ---- static scratch ----
__device__ float d_deg[CN];
__device__ int   d_cnt[CN];
__device__ float d_dinv[CN];
__device__ int   d_bsum[NB];
__device__ int   d_boff[NB];
__device__ int   d_ptr[CN + 1];
__device__ int   d_pos[CN];
__device__ int   d_csrc[CE];
__device__ float d_cw[CE];
__device__ float d_hw[(size_t)2 * CN * 64];    // [c][n][64]
__device__ float d_agg[(size_t)2 * CN * 64];   // [c][n][64]
__device__ float d_g[(size_t)CN * 64];         // merged layer-2 input
__device__ float d_emb[(size_t)CN * 64];
__device__ float d_stats[256];                 // [c][sum64|sumsq64]
__device__ float d_ss[256];                    // [c][scale64|shift64]

// ---- init: deg=1 (self loop), cnt=0, stats=0 ----
__global__ void init_k() {
    int n = blockIdx.x * 256 + threadIdx.x;
    if (n < CN) { d_deg[n] = 1.0f; d_cnt[n] = 0; }
    if (blockIdx.x == 0) d_stats[threadIdx.x] = 0.0f;
}

// ---- edge pass 1: weighted degree + dst histogram ----
__global__ void edge1_k(const int* __restrict__ dst, const float* __restrict__ ew) {
    int e = blockIdx.x * 256 + threadIdx.x;
    if (e < CE) {
        int d = dst[e];
        atomicAdd(&d_deg[d], ew[e]);
        atomicAdd(&d_cnt[d], 1);
    }
}

__global__ void dinv_k() {
    int n = blockIdx.x * 256 + threadIdx.x;
    if (n < CN) d_dinv[n] = rsqrtf(d_deg[n]);
}

// ---- 2-level exclusive scan of d_cnt -> d_ptr ----
__global__ __launch_bounds__(256) void scan1_k() {
    __shared__ int sh[256];
    int i = blockIdx.x * 256 + threadIdx.x;
    sh[threadIdx.x] = (i < CN) ? d_cnt[i] : 0;
    __syncthreads();
    for (int off = 128; off; off >>= 1) {
        if (threadIdx.x < off) sh[threadIdx.x] += sh[threadIdx.x + off];
        __syncthreads();
    }
    if (threadIdx.x == 0) d_bsum[blockIdx.x] = sh[0];
}

__global__ __launch_bounds__(512) void scan2_k() {
    __shared__ int sh[512];
    int t = threadIdx.x;
    int v = (t < NB) ? d_bsum[t] : 0;
    sh[t] = v;
    __syncthreads();
    for (int off = 1; off < 512; off <<= 1) {
        int u = (t >= off) ? sh[t - off] : 0;
        __syncthreads();
        sh[t] += u;
        __syncthreads();
    }
    if (t < NB) d_boff[t] = sh[t] - v;
    if (t == 511) d_ptr[CN] = sh[511];
}

__global__ __launch_bounds__(256) void scan3_k() {
    __shared__ int sh[256];
    int t = threadIdx.x;
    int i = blockIdx.x * 256 + t;
    int v = (i < CN) ? d_cnt[i] : 0;
    sh[t] = v;
    __syncthreads();
    for (int off = 1; off < 256; off <<= 1) {
        int u = (t >= off) ? sh[t - off] : 0;
        __syncthreads();
        sh[t] += u;
        __syncthreads();
    }
    if (i < CN) {
        int p = d_boff[blockIdx.x] + sh[t] - v;
        d_ptr[i] = p;
        d_pos[i] = p;
    }
}

// ---- CSR fill: edges sorted by dst; weight = dinv[s]*ew*dinv[d] ----
__global__ void fill_k(const int* __restrict__ src, const int* __restrict__ dst,
                       const float* __restrict__ ew) {
    int e = blockIdx.x * 256 + threadIdx.x;
    if (e >= CE) return;
    int s = src[e], d = dst[e];
    float w = d_dinv[s] * ew[e] * d_dinv[d];
    int p = atomicAdd(&d_pos[d], 1);
    d_csrc[p] = s;
    d_cw[p] = w;
}

// ---- GEMM layer 1: hw_c = x_c @ W1  (gridDim.y = channel) ----
__global__ __launch_bounds__(256) void gemm0_k(const float* __restrict__ x,
                                               const float* __restrict__ W) {
    __shared__ float4 Ws[1024];
    int tid = threadIdx.x, c = blockIdx.y;
    const float4* Wv = (const float4*)W;
    #pragma unroll
    for (int i = 0; i < 4; i++) Ws[tid + i * 256] = Wv[tid + i * 256];
    __syncthreads();
    int n = blockIdx.x * 256 + tid;
    if (n >= CN) return;
    const float* row = x + (size_t)n * 128 + c * 64;
    float4 acc[16];
    #pragma unroll
    for (int j = 0; j < 16; j++) acc[j] = make_float4(0.f, 0.f, 0.f, 0.f);
    #pragma unroll
    for (int ch = 0; ch < 4; ch++) {
        float4 r[4];
        #pragma unroll
        for (int u = 0; u < 4; u++) r[u] = *(const float4*)(row + ch * 16 + u * 4);
        #pragma unroll
        for (int kk = 0; kk < 16; kk++) {
            float xk = ((const float*)r)[kk];
            int k = ch * 16 + kk;
            #pragma unroll
            for (int j = 0; j < 16; j++) {
                float4 w = Ws[k * 16 + j];
                acc[j].x = fmaf(xk, w.x, acc[j].x);
                acc[j].y = fmaf(xk, w.y, acc[j].y);
                acc[j].z = fmaf(xk, w.z, acc[j].z);
                acc[j].w = fmaf(xk, w.w, acc[j].w);
            }
        }
    }
    float4* o = (float4*)(d_hw + ((size_t)c * CN + n) * 64);
    #pragma unroll
    for (int j = 0; j < 16; j++) o[j] = acc[j];
}

// ---- agg layer 1 (both channels, fused self-loop+bias+stats) ----
// warp per node: lane -> (channel = lane>>4, chunk = lane&15)
__global__ __launch_bounds__(256) void agg1_k(const float* __restrict__ b1) {
    __shared__ float sb[64];
    __shared__ float psum[8 * 128];
    __shared__ float psq[8 * 128];
    int tid = threadIdx.x;
    if (tid < 64) sb[tid] = b1[tid];
    __syncthreads();
    int w = tid >> 5, lane = tid & 31;
    int c = lane >> 4, qq = lane & 15;
    int n = blockIdx.x * 8 + w;                       // 12500*8 == CN
    const float* hwb = d_hw + (size_t)c * CN * 64;
    float dv = d_dinv[n], sn = dv * dv;
    float4 self = *(const float4*)(hwb + (size_t)n * 64 + qq * 4);
    float4 b4 = *(const float4*)(sb + qq * 4);
    float4 acc;
    acc.x = fmaf(sn, self.x, b4.x);
    acc.y = fmaf(sn, self.y, b4.y);
    acc.z = fmaf(sn, self.z, b4.z);
    acc.w = fmaf(sn, self.w, b4.w);
    int beg = d_ptr[n], end = d_ptr[n + 1];
    for (int i = beg; i < end; i += 4) {
        #pragma unroll
        for (int k = 0; k < 4; k++) {
            int idx = i + k;
            if (idx < end) {
                int s = d_csrc[idx];
                float ww = d_cw[idx];
                float4 v = *(const float4*)(hwb + (size_t)s * 64 + qq * 4);
                acc.x = fmaf(ww, v.x, acc.x);
                acc.y = fmaf(ww, v.y, acc.y);
                acc.z = fmaf(ww, v.z, acc.z);
                acc.w = fmaf(ww, v.w, acc.w);
            }
        }
    }
    *(float4*)(d_agg + ((size_t)c * CN + n) * 64 + qq * 4) = acc;
    float* ps = psum + w * 128 + c * 64 + qq * 4;
    float* pq = psq + w * 128 + c * 64 + qq * 4;
    ps[0] = acc.x; ps[1] = acc.y; ps[2] = acc.z; ps[3] = acc.w;
    pq[0] = acc.x * acc.x; pq[1] = acc.y * acc.y;
    pq[2] = acc.z * acc.z; pq[3] = acc.w * acc.w;
    __syncthreads();
    if (tid < 128) {
        float s = 0.f, q = 0.f;
        #pragma unroll
        for (int u = 0; u < 8; u++) { s += psum[u * 128 + tid]; q += psq[u * 128 + tid]; }
        int c2 = tid >> 6, f = tid & 63;
        atomicAdd(&d_stats[c2 * 128 + f], s);
        atomicAdd(&d_stats[c2 * 128 + 64 + f], q);
    }
}

// ---- GraphNorm finalize (both channels) ----
__global__ void finalize_k(const float* __restrict__ gnw, const float* __restrict__ gnb,
                           const float* __restrict__ gnms) {
    int tid = threadIdx.x;                 // 128
    int c = tid >> 6, f = tid & 63;
    const float invN = 1.0f / CN;
    float mean = d_stats[c * 128 + f] * invN;
    float ex2 = d_stats[c * 128 + 64 + f] * invN;
    float ms = gnms[f];
    float var = ex2 - ms * (2.0f - ms) * mean * mean;
    float scale = gnw[f] * rsqrtf(var + 1e-5f);
    d_ss[c * 128 + f] = scale;
    d_ss[c * 128 + 64 + f] = gnb[f] - scale * ms * mean;
}

// ---- GEMM layer 2 (merged channels): g = (0.5*(relu(gn0)+relu(gn1))) @ W2 ----
__global__ __launch_bounds__(256) void gemm1_k(const float* __restrict__ W) {
    __shared__ float4 Ws[1024];
    __shared__ float sc0[64], sh0[64], sc1[64], sh1[64];
    int tid = threadIdx.x;
    const float4* Wv = (const float4*)W;
    #pragma unroll
    for (int i = 0; i < 4; i++) Ws[tid + i * 256] = Wv[tid + i * 256];
    if (tid < 64) {
        sc0[tid] = d_ss[tid];        sh0[tid] = d_ss[64 + tid];
        sc1[tid] = d_ss[128 + tid];  sh1[tid] = d_ss[192 + tid];
    }
    __syncthreads();
    int n = blockIdx.x * 256 + tid;
    if (n >= CN) return;
    const float* r0 = d_agg + (size_t)n * 64;
    const float* r1 = d_agg + ((size_t)CN + n) * 64;
    float4 acc[16];
    #pragma unroll
    for (int j = 0; j < 16; j++) acc[j] = make_float4(0.f, 0.f, 0.f, 0.f);
    #pragma unroll
    for (int ch = 0; ch < 4; ch++) {
        float4 a0[4], a1[4];
        #pragma unroll
        for (int u = 0; u < 4; u++) {
            a0[u] = *(const float4*)(r0 + ch * 16 + u * 4);
            a1[u] = *(const float4*)(r1 + ch * 16 + u * 4);
        }
        #pragma unroll
        for (int kk = 0; kk < 16; kk++) {
            int k = ch * 16 + kk;
            float v0 = ((const float*)a0)[kk];
            float v1 = ((const float*)a1)[kk];
            float xk = 0.5f * (fmaxf(fmaf(sc0[k], v0, sh0[k]), 0.f) +
                               fmaxf(fmaf(sc1[k], v1, sh1[k]), 0.f));
            #pragma unroll
            for (int j = 0; j < 16; j++) {
                float4 w = Ws[k * 16 + j];
                acc[j].x = fmaf(xk, w.x, acc[j].x);
                acc[j].y = fmaf(xk, w.y, acc[j].y);
                acc[j].z = fmaf(xk, w.z, acc[j].z);
                acc[j].w = fmaf(xk, w.w, acc[j].w);
            }
        }
    }
    float4* o = (float4*)(d_g + (size_t)n * 64);
    #pragma unroll
    for (int j = 0; j < 16; j++) o[j] = acc[j];
}

// ---- agg layer 2 (merged): emb = sn*g + b2 + sum(w * g[src]) ----
__global__ __launch_bounds__(256) void agg2_k(const float* __restrict__ b2) {
    __shared__ float sb[64];
    if (threadIdx.x < 64) sb[threadIdx.x] = b2[threadIdx.x];
    __syncthreads();
    int slot = threadIdx.x >> 4, qq = threadIdx.x & 15;
    int n = blockIdx.x * 16 + slot;                   // 6250*16 == CN
    float dv = d_dinv[n], sn = dv * dv;
    float4 self = *(const float4*)(d_g + (size_t)n * 64 + qq * 4);
    float4 b4 = *(const float4*)(sb + qq * 4);
    float4 acc;
    acc.x = fmaf(sn, self.x, b4.x);
    acc.y = fmaf(sn, self.y, b4.y);
    acc.z = fmaf(sn, self.z, b4.z);
    acc.w = fmaf(sn, self.w, b4.w);
    int beg = d_ptr[n], end = d_ptr[n + 1];
    for (int i = beg; i < end; i += 4) {
        #pragma unroll
        for (int k = 0; k < 4; k++) {
            int idx = i + k;
            if (idx < end) {
                int s = d_csrc[idx];
                float ww = d_cw[idx];
                float4 v = *(const float4*)(d_g + (size_t)s * 64 + qq * 4);
                acc.x = fmaf(ww, v.x, acc.x);
                acc.y = fmaf(ww, v.y, acc.y);
                acc.z = fmaf(ww, v.z, acc.z);
                acc.w = fmaf(ww, v.w, acc.w);
            }
        }
    }
    *(float4*)(d_emb + (size_t)n * 64 + qq * 4) = acc;
}

// ---- subgraph pool + MLP ----
__global__ __launch_bounds__(128) void pool_k(const int* __restrict__ subG,
                                              const float* __restrict__ mW1,
                                              const float* __restrict__ mb1,
                                              const float* __restrict__ mW2,
                                              const float* __restrict__ mb2,
                                              float* __restrict__ out) {
    __shared__ float Wm[64 * 128];
    __shared__ float pooled[64];
    __shared__ float ptmp[128];
    __shared__ float red[4];
    int tid = threadIdx.x, s = blockIdx.x;
    const float4* wv = (const float4*)mW1;
    #pragma unroll
    for (int i = 0; i < 16; i++) ((float4*)Wm)[tid + i * 128] = wv[tid + i * 128];
    int j = tid & 63, half = tid >> 6;
    float p = 0.f;
    #pragma unroll 4
    for (int m = half * 32; m < half * 32 + 32; m++) {
        int node = subG[s * 64 + m];
        p += d_emb[(size_t)node * 64 + j];
    }
    ptmp[tid] = p;
    __syncthreads();
    if (tid < 64) pooled[tid] = ptmp[tid] + ptmp[tid + 64];
    __syncthreads();
    float acc = mb1[tid];
    #pragma unroll 8
    for (int o = 0; o < 64; o++) acc = fmaf(pooled[o], Wm[o * 128 + tid], acc);
    float contrib = fmaxf(acc, 0.f) * mW2[tid];
    #pragma unroll
    for (int off = 16; off; off >>= 1) contrib += __shfl_xor_sync(0xffffffffu, contrib, off);
    if ((tid & 31) == 0) red[tid >> 5] = contrib;
    __syncthreads();
    if (tid == 0) out[s] = red[0] + red[1] + red[2] + red[3] + mb2[0];
}

extern "C" void kernel_launch(void* const* d_in, const int* in_sizes, int n_in,
                              void* d_out, int out_size) {
    const float* x    = (const float*)d_in[0];
    const int*   ei   = (const int*)d_in[1];
    const float* ew   = (const float*)d_in[2];
    const int*   subG = (const int*)d_in[3];
    const float* W1   = (const float*)d_in[4];
    const float* b1   = (const float*)d_in[5];
    const float* gnw  = (const float*)d_in[6];
    const float* gnb  = (const float*)d_in[7];
    const float* gnms = (const float*)d_in[8];
    const float* W2   = (const float*)d_in[9];
    const float* b2   = (const float*)d_in[10];
    const float* mW1  = (const float*)d_in[11];
    const float* mb1  = (const float*)d_in[12];
    const float* mW2  = (const float*)d_in[13];
    const float* mb2  = (const float*)d_in[14];
    float* out = (float*)d_out;
    const int* src = ei;
    const int* dst = ei + CE;

    const int eb = (CE + 255) / 256;

    init_k<<<NB, 256>>>();
    edge1_k<<<eb, 256>>>(dst, ew);
    dinv_k<<<NB, 256>>>();
    scan1_k<<<NB, 256>>>();
    scan2_k<<<1, 512>>>();
    scan3_k<<<NB, 256>>>();
    fill_k<<<eb, 256>>>(src, dst, ew);

    dim3 g0(NB, 2);
    gemm0_k<<<g0, 256>>>(x, W1);
    agg1_k<<<CN / 8, 256>>>(b1);
    finalize_k<<<1, 128>>>(gnw, gnb, gnms);
    gemm1_k<<<NB, 256>>>(W2);
    agg2_k<<<CN / 16, 256>>>(b2);
    pool_k<<<1000, 128>>>(subG, mW1, mb1, mW2, mb2, out);
}

// round 3
// speedup vs baseline: 1.9867x; 1.0463x over previous
#include <cuda_runtime.h>

#define CN 100000
#define CE 1600000
#define NB 391            // ceil(CN/256)

typedef unsigned long long ull;

// ---- static scratch ----
__device__ ull   d_degcnt[CN];                 // hi32: cnt, lo32: fixed-point deg sum
__device__ float d_dinv[CN];
__device__ int   d_bsum[NB];
__device__ int   d_ptr[CN + 1];
__device__ int   d_pos[CN];
__device__ int   d_csrc[CE];
__device__ float d_cw[CE];
__device__ float d_hw[(size_t)2 * CN * 64];    // dinv-scaled: hws = dinv*(x@W1)
__device__ float d_agg[(size_t)2 * CN * 64];
__device__ float d_g[(size_t)CN * 64];         // dinv-scaled layer-2 product
__device__ float d_emb[(size_t)CN * 64];
__device__ float d_stats[256];                 // [c][sum64|sumsq64]

// ---- packed f32x2 helpers ----
__device__ __forceinline__ ull pk2(float a, float b) {
    ull r; asm("mov.b64 %0, {%1, %2};" : "=l"(r) : "f"(a), "f"(b)); return r;
}
__device__ __forceinline__ void upk2(ull v, float& a, float& b) {
    asm("mov.b64 {%0, %1}, %2;" : "=f"(a), "=f"(b) : "l"(v));
}
__device__ __forceinline__ ull ffma2(ull a, ull b, ull c) {
    ull d; asm("fma.rn.f32x2 %0, %1, %2, %3;" : "=l"(d) : "l"(a), "l"(b), "l"(c)); return d;
}
__device__ __forceinline__ ull fmul2(ull a, ull b) {
    ull d; asm("mul.rn.f32x2 %0, %1, %2;" : "=l"(d) : "l"(a), "l"(b)); return d;
}

// ---- init ----
__global__ void init_k() {
    int n = blockIdx.x * 256 + threadIdx.x;
    if (n < CN) d_degcnt[n] = 0ull;
    if (blockIdx.x == 0) d_stats[threadIdx.x] = 0.0f;
}

// ---- edge pass 1: packed (cnt, fixed-point weighted degree) histogram ----
__global__ void edge1_k(const int* __restrict__ dst, const float* __restrict__ ew) {
    int e = blockIdx.x * 256 + threadIdx.x;
    if (e < CE) {
        unsigned fx = (unsigned)__float2uint_rn(ew[e] * 16777216.0f);
        atomicAdd(&d_degcnt[dst[e]], (1ull << 32) | (ull)fx);
    }
}

// ---- scan1: dinv + per-block count sums ----
__global__ __launch_bounds__(256) void scan1_k() {
    __shared__ int sh[256];
    int i = blockIdx.x * 256 + threadIdx.x;
    int cnt = 0;
    if (i < CN) {
        ull dc = d_degcnt[i];
        cnt = (int)(dc >> 32);
        float deg = 1.0f + (float)(unsigned)dc * 5.9604644775390625e-8f;
        d_dinv[i] = rsqrtf(deg);
    }
    sh[threadIdx.x] = cnt;
    __syncthreads();
    for (int off = 128; off; off >>= 1) {
        if (threadIdx.x < off) sh[threadIdx.x] += sh[threadIdx.x + off];
        __syncthreads();
    }
    if (threadIdx.x == 0) d_bsum[blockIdx.x] = sh[0];
}

// ---- scan3: per-block offset (redundant reduce of bsum) + local scan -> ptr/pos ----
__global__ __launch_bounds__(256) void scan3_k() {
    __shared__ int red[256];
    __shared__ int sh[256];
    __shared__ int boff_s;
    int t = threadIdx.x, b = blockIdx.x;
    int s = 0;
    if (t < b && t < NB) s = d_bsum[t];
    if (t + 256 < b) s += d_bsum[t + 256];
    red[t] = s;
    __syncthreads();
    for (int off = 128; off; off >>= 1) {
        if (t < off) red[t] += red[t + off];
        __syncthreads();
    }
    if (t == 0) boff_s = red[0];
    int i = b * 256 + t;
    int v = (i < CN) ? (int)(d_degcnt[i] >> 32) : 0;
    sh[t] = v;
    __syncthreads();
    for (int off = 1; off < 256; off <<= 1) {
        int u = (t >= off) ? sh[t - off] : 0;
        __syncthreads();
        sh[t] += u;
        __syncthreads();
    }
    if (i < CN) {
        int p = boff_s + sh[t] - v;       // exclusive
        d_ptr[i] = p;
        d_pos[i] = p;
        if (i == CN - 1) d_ptr[CN] = p + v;
    }
}

// ---- CSR fill: raw edge weight (no dinv) ----
__global__ void fill_k(const int* __restrict__ src, const int* __restrict__ dst,
                       const float* __restrict__ ew) {
    int e = blockIdx.x * 256 + threadIdx.x;
    if (e >= CE) return;
    int d = dst[e];
    int p = atomicAdd(&d_pos[d], 1);
    d_csrc[p] = src[e];
    d_cw[p] = ew[e];
}

// ---- GEMM layer 1: hws_c = dinv * (x_c @ W1)  (gridDim.y = channel) ----
__global__ __launch_bounds__(256) void gemm0_k(const float* __restrict__ x,
                                               const float* __restrict__ W) {
    __shared__ ull Ws2[2048];                 // 64x64 fp32 as 64x32 pairs
    int tid = threadIdx.x, c = blockIdx.y;
    const float4* Wv = (const float4*)W;
    float4* Wsf = (float4*)Ws2;
    #pragma unroll
    for (int i = 0; i < 4; i++) Wsf[tid + i * 256] = Wv[tid + i * 256];
    __syncthreads();
    int n = blockIdx.x * 256 + tid;
    if (n >= CN) return;
    const float* row = x + (size_t)n * 128 + c * 64;
    ull acc[32];
    #pragma unroll
    for (int j = 0; j < 32; j++) acc[j] = 0ull;
    #pragma unroll
    for (int ch = 0; ch < 4; ch++) {
        float4 r[4];
        #pragma unroll
        for (int u = 0; u < 4; u++) r[u] = *(const float4*)(row + ch * 16 + u * 4);
        #pragma unroll
        for (int kk = 0; kk < 16; kk++) {
            int k = ch * 16 + kk;
            float xk = ((const float*)r)[kk];
            ull xk2 = pk2(xk, xk);
            const ulonglong2* wr = (const ulonglong2*)(Ws2 + k * 32);
            #pragma unroll
            for (int j8 = 0; j8 < 16; j8++) {
                ulonglong2 w = wr[j8];
                acc[2 * j8]     = ffma2(xk2, w.x, acc[2 * j8]);
                acc[2 * j8 + 1] = ffma2(xk2, w.y, acc[2 * j8 + 1]);
            }
        }
    }
    float dv = d_dinv[n];
    ull dv2 = pk2(dv, dv);
    ulonglong2* o = (ulonglong2*)(d_hw + ((size_t)c * CN + n) * 64);
    #pragma unroll
    for (int j8 = 0; j8 < 16; j8++) {
        ulonglong2 w;
        w.x = fmul2(acc[2 * j8], dv2);
        w.y = fmul2(acc[2 * j8 + 1], dv2);
        o[j8] = w;
    }
}

// ---- agg layer 1 (both channels): agg = dinv*(sum ew*hws[src] + hws[n]) + b1, + stats ----
__global__ __launch_bounds__(256) void agg1_k(const float* __restrict__ b1) {
    __shared__ float sb[64];
    __shared__ float psum[8 * 128];
    __shared__ float psq[8 * 128];
    int tid = threadIdx.x;
    if (tid < 64) sb[tid] = b1[tid];
    __syncthreads();
    int w = tid >> 5, lane = tid & 31;
    int c = lane >> 4, qq = lane & 15;
    int n = blockIdx.x * 8 + w;                       // 12500*8 == CN
    const float* hwb = d_hw + (size_t)c * CN * 64;
    float4 acc = *(const float4*)(hwb + (size_t)n * 64 + qq * 4);   // self term (hws[n])
    int beg = d_ptr[n], end = d_ptr[n + 1];
    for (int i = beg; i < end; i += 4) {
        #pragma unroll
        for (int k = 0; k < 4; k++) {
            int idx = i + k;
            if (idx < end) {
                int s = d_csrc[idx];
                float ww = d_cw[idx];
                float4 v = *(const float4*)(hwb + (size_t)s * 64 + qq * 4);
                acc.x = fmaf(ww, v.x, acc.x);
                acc.y = fmaf(ww, v.y, acc.y);
                acc.z = fmaf(ww, v.z, acc.z);
                acc.w = fmaf(ww, v.w, acc.w);
            }
        }
    }
    float dv = d_dinv[n];
    float4 b4 = *(const float4*)(sb + qq * 4);
    float4 fin;
    fin.x = fmaf(dv, acc.x, b4.x);
    fin.y = fmaf(dv, acc.y, b4.y);
    fin.z = fmaf(dv, acc.z, b4.z);
    fin.w = fmaf(dv, acc.w, b4.w);
    *(float4*)(d_agg + ((size_t)c * CN + n) * 64 + qq * 4) = fin;
    float* ps = psum + w * 128 + c * 64 + qq * 4;
    float* pq = psq + w * 128 + c * 64 + qq * 4;
    ps[0] = fin.x; ps[1] = fin.y; ps[2] = fin.z; ps[3] = fin.w;
    pq[0] = fin.x * fin.x; pq[1] = fin.y * fin.y;
    pq[2] = fin.z * fin.z; pq[3] = fin.w * fin.w;
    __syncthreads();
    if (tid < 128) {
        float s = 0.f, q = 0.f;
        #pragma unroll
        for (int u = 0; u < 8; u++) { s += psum[u * 128 + tid]; q += psq[u * 128 + tid]; }
        int c2 = tid >> 6, f = tid & 63;
        atomicAdd(&d_stats[c2 * 128 + f], s);
        atomicAdd(&d_stats[c2 * 128 + 64 + f], q);
    }
}

// ---- GEMM layer 2 (+fused GraphNorm finalize): g = dinv * ((0.5*(relu0+relu1)) @ W2) ----
__global__ __launch_bounds__(256) void gemm1_k(const float* __restrict__ W,
                                               const float* __restrict__ gnw,
                                               const float* __restrict__ gnb,
                                               const float* __restrict__ gnms) {
    __shared__ ull Ws2[2048];
    __shared__ float sc0[64], sh0[64], sc1[64], sh1[64];
    int tid = threadIdx.x;
    const float4* Wv = (const float4*)W;
    float4* Wsf = (float4*)Ws2;
    #pragma unroll
    for (int i = 0; i < 4; i++) Wsf[tid + i * 256] = Wv[tid + i * 256];
    if (tid < 128) {
        int c = tid >> 6, f = tid & 63;
        const float invN = 1.0f / CN;
        float mean = d_stats[c * 128 + f] * invN;
        float ex2 = d_stats[c * 128 + 64 + f] * invN;
        float ms = gnms[f];
        float var = ex2 - ms * (2.0f - ms) * mean * mean;
        float scale = gnw[f] * rsqrtf(var + 1e-5f);
        float shift = gnb[f] - scale * ms * mean;
        if (c == 0) { sc0[f] = scale; sh0[f] = shift; }
        else        { sc1[f] = scale; sh1[f] = shift; }
    }
    __syncthreads();
    int n = blockIdx.x * 256 + tid;
    if (n >= CN) return;
    const float* r0 = d_agg + (size_t)n * 64;
    const float* r1 = d_agg + ((size_t)CN + n) * 64;
    ull acc[32];
    #pragma unroll
    for (int j = 0; j < 32; j++) acc[j] = 0ull;
    #pragma unroll
    for (int ch = 0; ch < 4; ch++) {
        float4 a0[4], a1[4];
        #pragma unroll
        for (int u = 0; u < 4; u++) {
            a0[u] = *(const float4*)(r0 + ch * 16 + u * 4);
            a1[u] = *(const float4*)(r1 + ch * 16 + u * 4);
        }
        #pragma unroll
        for (int kk = 0; kk < 16; kk++) {
            int k = ch * 16 + kk;
            float v0 = ((const float*)a0)[kk];
            float v1 = ((const float*)a1)[kk];
            float xk = 0.5f * (fmaxf(fmaf(sc0[k], v0, sh0[k]), 0.f) +
                               fmaxf(fmaf(sc1[k], v1, sh1[k]), 0.f));
            ull xk2 = pk2(xk, xk);
            const ulonglong2* wr = (const ulonglong2*)(Ws2 + k * 32);
            #pragma unroll
            for (int j8 = 0; j8 < 16; j8++) {
                ulonglong2 w = wr[j8];
                acc[2 * j8]     = ffma2(xk2, w.x, acc[2 * j8]);
                acc[2 * j8 + 1] = ffma2(xk2, w.y, acc[2 * j8 + 1]);
            }
        }
    }
    float dv = d_dinv[n];
    ull dv2 = pk2(dv, dv);
    ulonglong2* o = (ulonglong2*)(d_g + (size_t)n * 64);
    #pragma unroll
    for (int j8 = 0; j8 < 16; j8++) {
        ulonglong2 w;
        w.x = fmul2(acc[2 * j8], dv2);
        w.y = fmul2(acc[2 * j8 + 1], dv2);
        o[j8] = w;
    }
}

// ---- agg layer 2: emb = dinv*(sum ew*g[src] + g[n]) + b2 ----
__global__ __launch_bounds__(256) void agg2_k(const float* __restrict__ b2) {
    __shared__ float sb[64];
    if (threadIdx.x < 64) sb[threadIdx.x] = b2[threadIdx.x];
    __syncthreads();
    int slot = threadIdx.x >> 4, qq = threadIdx.x & 15;
    int n = blockIdx.x * 16 + slot;                   // 6250*16 == CN
    float4 acc = *(const float4*)(d_g + (size_t)n * 64 + qq * 4);   // self
    int beg = d_ptr[n], end = d_ptr[n + 1];
    for (int i = beg; i < end; i += 4) {
        #pragma unroll
        for (int k = 0; k < 4; k++) {
            int idx = i + k;
            if (idx < end) {
                int s = d_csrc[idx];
                float ww = d_cw[idx];
                float4 v = *(const float4*)(d_g + (size_t)s * 64 + qq * 4);
                acc.x = fmaf(ww, v.x, acc.x);
                acc.y = fmaf(ww, v.y, acc.y);
                acc.z = fmaf(ww, v.z, acc.z);
                acc.w = fmaf(ww, v.w, acc.w);
            }
        }
    }
    float dv = d_dinv[n];
    float4 b4 = *(const float4*)(sb + qq * 4);
    float4 fin;
    fin.x = fmaf(dv, acc.x, b4.x);
    fin.y = fmaf(dv, acc.y, b4.y);
    fin.z = fmaf(dv, acc.z, b4.z);
    fin.w = fmaf(dv, acc.w, b4.w);
    *(float4*)(d_emb + (size_t)n * 64 + qq * 4) = fin;
}

// ---- subgraph pool + MLP ----
__global__ __launch_bounds__(128) void pool_k(const int* __restrict__ subG,
                                              const float* __restrict__ mW1,
                                              const float* __restrict__ mb1,
                                              const float* __restrict__ mW2,
                                              const float* __restrict__ mb2,
                                              float* __restrict__ out) {
    __shared__ float Wm[64 * 128];
    __shared__ float pooled[64];
    __shared__ float ptmp[128];
    __shared__ float red[4];
    int tid = threadIdx.x, s = blockIdx.x;
    const float4* wv = (const float4*)mW1;
    #pragma unroll
    for (int i = 0; i < 16; i++) ((float4*)Wm)[tid + i * 128] = wv[tid + i * 128];
    int j = tid & 63, half = tid >> 6;
    float p = 0.f;
    #pragma unroll 4
    for (int m = half * 32; m < half * 32 + 32; m++) {
        int node = subG[s * 64 + m];
        p += d_emb[(size_t)node * 64 + j];
    }
    ptmp[tid] = p;
    __syncthreads();
    if (tid < 64) pooled[tid] = ptmp[tid] + ptmp[tid + 64];
    __syncthreads();
    float acc = mb1[tid];
    #pragma unroll 8
    for (int o = 0; o < 64; o++) acc = fmaf(pooled[o], Wm[o * 128 + tid], acc);
    float contrib = fmaxf(acc, 0.f) * mW2[tid];
    #pragma unroll
    for (int off = 16; off; off >>= 1) contrib += __shfl_xor_sync(0xffffffffu, contrib, off);
    if ((tid & 31) == 0) red[tid >> 5] = contrib;
    __syncthreads();
    if (tid == 0) out[s] = red[0] + red[1] + red[2] + red[3] + mb2[0];
}

extern "C" void kernel_launch(void* const* d_in, const int* in_sizes, int n_in,
                              void* d_out, int out_size) {
    const float* x    = (const float*)d_in[0];
    const int*   ei   = (const int*)d_in[1];
    const float* ew   = (const float*)d_in[2];
    const int*   subG = (const int*)d_in[3];
    const float* W1   = (const float*)d_in[4];
    const float* b1   = (const float*)d_in[5];
    const float* gnw  = (const float*)d_in[6];
    const float* gnb  = (const float*)d_in[7];
    const float* gnms = (const float*)d_in[8];
    const float* W2   = (const float*)d_in[9];
    const float* b2   = (const float*)d_in[10];
    const float* mW1  = (const float*)d_in[11];
    const float* mb1  = (const float*)d_in[12];
    const float* mW2  = (const float*)d_in[13];
    const float* mb2  = (const float*)d_in[14];
    float* out = (float*)d_out;
    const int* src = ei;
    const int* dst = ei + CE;

    const int eb = (CE + 255) / 256;

    init_k<<<NB, 256>>>();
    edge1_k<<<eb, 256>>>(dst, ew);
    scan1_k<<<NB, 256>>>();
    scan3_k<<<NB, 256>>>();
    fill_k<<<eb, 256>>>(src, dst, ew);

    dim3 g0(NB, 2);
    gemm0_k<<<g0, 256>>>(x, W1);
    agg1_k<<<CN / 8, 256>>>(b1);
    gemm1_k<<<NB, 256>>>(W2, gnw, gnb, gnms);
    agg2_k<<<CN / 16, 256>>>(b2);
    pool_k<<<1000, 128>>>(subG, mW1, mb1, mW2, mb2, out);
}